// round 10
// baseline (speedup 1.0000x reference)
#include <cuda_runtime.h>
#include <cuda_fp16.h>

// Edge_27547920236817: B=16, C=3, H=W=512 f32 in; out (B, C*8, H, W) f32.
// R7 (= R4 with compile fix): 2 x-adjacent pixels per thread; the 22 unique
// e-sum tanh terms computed as tanh.approx.f16x2 (args packed across the
// pixel pair), unpacked and summed in f32. Gates, sign sigmoids and
// ad-multiplier tanhs remain f32 MUFU.TANH.
// MUFU per pixel: 33 -> 22 (11 f16x2-halves + 11 f32).
// Memory instrs per pixel: 19 LDG + 8 STG -> 11 LDG + 4 STG.64.

#define HH 512
#define WW 512

__device__ __forceinline__ float th(float x) {
    float y;
    asm("tanh.approx.f32 %0, %1;" : "=f"(y) : "f"(x));
    return y;
}

// tanh.approx.f16x2 on (a0, a1); accumulate w*tanh into f32 sums T[0], T[1]
__device__ __forceinline__ void acc2(float* T, float a0, float a1, float w = 1.0f) {
    __half2 h = __floats2half2_rn(a0, a1);
    unsigned uin, uout;
    uin = *reinterpret_cast<unsigned*>(&h);
    asm("tanh.approx.f16x2 %0, %1;" : "=r"(uout) : "r"(uin));
    __half2 t = *reinterpret_cast<__half2*>(&uout);
    float2 tf = __half22float2(t);
    T[0] = fmaf(w, tf.x, T[0]);
    T[1] = fmaf(w, tf.y, T[1]);
}

__device__ __forceinline__ float2 ldg2(const float* p) {
    return *reinterpret_cast<const float2*>(p);
}

__global__ void __launch_bounds__(256) edge_kernel(const float* __restrict__ in,
                                                   float* __restrict__ out) {
    int idx = blockIdx.x * blockDim.x + threadIdx.x;   // one thread = 2 pixels
    int x  = (idx & 255) << 1;         // even
    int y  = (idx >> 8) & (HH - 1);
    int bc = idx >> 17;                // b*3 + c
    int c  = bc - (bc / 3) * 3;
    int b  = bc / 3;

    float* o = out + (((b * 24 + c * 8) << 18) + (y << 9) + x);

    if (x < 2 || x >= WW - 2 || y < 2 || y >= HH - 2) {
        float2 z = make_float2(0.0f, 0.0f);
        #pragma unroll
        for (int k = 0; k < 8; k++) *reinterpret_cast<float2*>(o + (k << 18)) = z;
        return;
    }

    int cm = (c + 2) % 3;
    int cp = (c + 1) % 3;

    const float* p  = in + (bc << 18);
    const float* pa = in + ((b * 3 + cm) << 18);
    const float* pc = in + ((b * 3 + cp) << 18);

    int r   = (y << 9) + x;
    int rm1 = r - WW, rp1 = r + WW, rm2 = r - 2 * WW;

    const float S = 5.0f;

    // ---- loads (pre-scaled by 5) ----
    // own channel
    float2 Vm2 = ldg2(p + rm2);         Vm2.x *= S; Vm2.y *= S;
    float  um1L = S * __ldg(p + rm1 - 1);
    float2 Um1  = ldg2(p + rm1);        Um1.x *= S; Um1.y *= S;
    float  um1R = S * __ldg(p + rm1 + 2);
    float  u0L  = S * __ldg(p + r - 1);
    float2 U0   = ldg2(p + r);          U0.x  *= S; U0.y  *= S;
    float  u0R  = S * __ldg(p + r + 2);
    float  up1L = S * __ldg(p + rp1 - 1);
    float2 Up1  = ldg2(p + rp1);        Up1.x *= S; Up1.y *= S;
    float  up1R = S * __ldg(p + rp1 + 2);
    // channel cm
    float  aL  = S * __ldg(pa + r - 1);
    float2 A0  = ldg2(pa + r);          A0.x *= S; A0.y *= S;
    float  aR  = S * __ldg(pa + r + 2);
    float2 Am1 = ldg2(pa + rm1);        Am1.x *= S; Am1.y *= S;
    float  a2L = S * __ldg(pa + rm2 - 1);
    float2 A2  = ldg2(pa + rm2);        A2.x *= S; A2.y *= S;
    float  a2R = S * __ldg(pa + rm2 + 2);
    // channel cp
    float2 Cm1 = ldg2(pc + rm1);        Cm1.x *= S; Cm1.y *= S;
    float  c2L = S * __ldg(pc + rm2 - 1);
    float  c2C = S * __ldg(pc + rm2);
    float  c0L = S * __ldg(pc + r - 1);
    float  c0C = S * __ldg(pc + r);

    // ---- per-lane neighborhoods ----
    float v00[2]   = { U0.x,  U0.y  };
    float v0m1[2]  = { u0L,   U0.x  };
    float v0p1[2]  = { U0.y,  u0R   };
    float vm1m1[2] = { um1L,  Um1.x };
    float vm10[2]  = { Um1.x, Um1.y };
    float vm1p1[2] = { Um1.y, um1R  };
    float vp1m1[2] = { up1L,  Up1.x };
    float vp10[2]  = { Up1.x, Up1.y };
    float vp1p1[2] = { Up1.y, up1R  };
    float vm20[2]  = { Vm2.x, Vm2.y };
    float a00[2]   = { A0.x,  A0.y  };
    float a0m1[2]  = { aL,    A0.x  };
    float a0p1[2]  = { A0.y,  aR    };
    float am10[2]  = { Am1.x, Am1.y };
    float am2m1[2] = { a2L,   A2.x  };
    float am2p1[2] = { A2.y,  a2R   };
    float cm10[2]  = { Cm1.x, Cm1.y };
    float cm2m1[2] = { c2L,   c2C   };
    float c0m1[2]  = { c0L,   c0C   };

    // ---- diffs (scaled) ----
    float d10[2], dn10[2], d01[2], dn01[2], d11[2], dnn11[2], dn11[2], d1n1[2];
    float rd01a[2], rdn01a[2], rd10u[2], rdn10u[2], rd01u[2];
    float rdn11b[2], rd1n1b[2], rd11b[2], rd11c[2], rdn11c[2];
    #pragma unroll
    for (int i = 0; i < 2; i++) {
        d10[i]   = vm10[i]  - v00[i];
        dn10[i]  = vp10[i]  - v00[i];
        d01[i]   = v0m1[i]  - v00[i];
        dn01[i]  = v0p1[i]  - v00[i];
        d11[i]   = vm1m1[i] - v00[i];
        dnn11[i] = vp1p1[i] - v00[i];
        dn11[i]  = vp1m1[i] - v00[i];
        d1n1[i]  = vm1p1[i] - v00[i];
        rd01a[i]  = a0m1[i] - a00[i];      // rl(.,(1,0))
        rdn01a[i] = a0p1[i] - a00[i];
        rd10u[i]  = vm20[i]  - vm10[i];    // rl(.,(0,1))
        rdn10u[i] = v00[i]   - vm10[i];
        rd01u[i]  = vm1m1[i] - vm10[i];
        rdn11b[i] = a0m1[i]  - am10[i];    // rl(.,(1,1))
        rd1n1b[i] = am2p1[i] - am10[i];
        rd11b[i]  = am2m1[i] - am10[i];
        rd11c[i]  = cm2m1[i] - cm10[i];    // rl(.,(-1,1))
        rdn11c[i] = c0m1[i]  - cm10[i];
    }

    // ---- per-lane ad bases (f32 tanh) ----
    float ad10[2], thad10[2], ad01[2], ad11[2], adn11[2];
    #pragma unroll
    for (int i = 0; i < 2; i++) {
        float ad10r = fabsf(d10[i]);
        ad10[i]  = ad10r * fmaf(0.5f, th(ad10r), 0.5f);
        thad10[i] = th(ad10[i]);
        ad01[i]  = fabsf(d01[i]) * fmaf(0.5f, thad10[i], 0.5f);
        float ad11r = fabsf(d11[i]);
        ad11[i]  = ad11r * fmaf(0.5f, th(ad11r), 0.5f);
        adn11[i] = fabsf(dn11[i]);
    }

    // ---- e-sums: f16x2 tanh terms, f32 accumulation ----
    float T10[2] = {0.f, 0.f}, T01[2] = {0.f, 0.f}, T11[2] = {0.f, 0.f}, Tn11[2] = {0.f, 0.f};

    acc2(T10, ad10[0] - fabsf(d01[0]),   ad10[1] - fabsf(d01[1]));
    acc2(T10, ad10[0] - fabsf(dn01[0]),  ad10[1] - fabsf(dn01[1]));
    acc2(T10, ad10[0] - fabsf(dn10[0]),  ad10[1] - fabsf(dn10[1]));
    acc2(T10, ad10[0] - fabsf(rd01a[0]), ad10[1] - fabsf(rd01a[1]), 2.0f);
    acc2(T10, ad10[0] - fabsf(rdn01a[0]),ad10[1] - fabsf(rdn01a[1]));

    acc2(T01, ad01[0] - fabsf(d10[0]),   ad01[1] - fabsf(d10[1]));
    acc2(T01, ad01[0] - fabsf(dn10[0]),  ad01[1] - fabsf(dn10[1]));
    acc2(T01, ad01[0] - fabsf(dn01[0]),  ad01[1] - fabsf(dn01[1]));
    acc2(T01, ad01[0] - fabsf(rd10u[0]), ad01[1] - fabsf(rd10u[1]));
    acc2(T01, ad01[0] - fabsf(rdn10u[0]),ad01[1] - fabsf(rdn10u[1]));
    acc2(T01, ad01[0] - fabsf(rd01u[0]), ad01[1] - fabsf(rd01u[1]));

    acc2(T11, ad11[0] - fabsf(dn11[0]),  ad11[1] - fabsf(dn11[1]));
    acc2(T11, ad11[0] - fabsf(d1n1[0]),  ad11[1] - fabsf(d1n1[1]));
    acc2(T11, ad11[0] - fabsf(dnn11[0]), ad11[1] - fabsf(dnn11[1]));
    acc2(T11, ad11[0] - fabsf(rdn11b[0]),ad11[1] - fabsf(rdn11b[1]));
    acc2(T11, ad11[0] - fabsf(rd1n1b[0]),ad11[1] - fabsf(rd1n1b[1]));
    acc2(T11, ad11[0] - fabsf(rd11b[0]), ad11[1] - fabsf(rd11b[1]));

    acc2(Tn11, adn11[0] - fabsf(d11[0]),   adn11[1] - fabsf(d11[1]));
    acc2(Tn11, adn11[0] - fabsf(d1n1[0]),  adn11[1] - fabsf(d1n1[1]));
    acc2(Tn11, adn11[0] - fabsf(dnn11[0]), adn11[1] - fabsf(dnn11[1]));
    acc2(Tn11, adn11[0] - fabsf(rd11c[0]), adn11[1] - fabsf(rd11c[1]));
    acc2(Tn11, adn11[0] - fabsf(rdn11c[0]),adn11[1] - fabsf(rdn11c[1]), 2.0f);

    // ---- gates + outputs (f32) ----
    float2 O[8];
    #pragma unroll
    for (int i = 0; i < 2; i++) {
        float g10 = fmaf(0.5f, th(fmaf(2.5f, T10[i], -5.0f)), 0.5f);
        float s10 = fmaf(0.5f, th(d10[i]), 0.5f);
        float g01 = fmaf(0.5f, th(fmaf(2.5f, T01[i], -5.0f)), 0.5f);
        float s01 = fmaf(0.5f, th(d01[i]), 0.5f);
        float g11 = fmaf(0.5f, th(fmaf(2.5f, T11[i], -5.0f)), 0.5f);
        float s11 = fmaf(0.5f, th(d11[i]), 0.5f);
        float gn11 = fmaf(0.5f, th(fmaf(2.5f, Tn11[i], -5.0f)), 0.5f);
        float sn11 = fmaf(0.5f, th(dn11[i]), 0.5f);
        float e0 = g10 * s10;
        float e2 = g01 * s01;
        float e4 = g11 * s11;
        float e6 = gn11 * sn11;
        float* oi = i ? &O[0].y : &O[0].x;
        oi[0*2] = e0;        oi[1*2] = g10 - e0;
        oi[2*2] = e2;        oi[3*2] = e2;        // reference quirk: e01n == e01
        oi[4*2] = e4;        oi[5*2] = g11 - e4;
        oi[6*2] = e6;        oi[7*2] = gn11 - e6;
    }

    #pragma unroll
    for (int k = 0; k < 8; k++)
        *reinterpret_cast<float2*>(o + (k << 18)) = O[k];
}

extern "C" void kernel_launch(void* const* d_in, const int* in_sizes, int n_in,
                              void* d_out, int out_size) {
    const float* x = (const float*)d_in[0];
    float* out = (float*)d_out;
    int total_threads = 16 * 3 * HH * (WW / 2);
    edge_kernel<<<total_threads / 256, 256>>>(x, out);
}

// round 11
// speedup vs baseline: 1.0003x; 1.0003x over previous
#include <cuda_runtime.h>
#include <cuda_fp16.h>

// Edge_27547920236817: B=16, C=3, H=W=512 f32 in; out (B, C*8, H, W) f32.
// R7 (= R4 with compile fix): 2 x-adjacent pixels per thread; the 22 unique
// e-sum tanh terms computed as tanh.approx.f16x2 (args packed across the
// pixel pair), unpacked and summed in f32. Gates, sign sigmoids and
// ad-multiplier tanhs remain f32 MUFU.TANH.
// MUFU per pixel: 33 -> 22 (11 f16x2-halves + 11 f32).
// Memory instrs per pixel: 19 LDG + 8 STG -> 11 LDG + 4 STG.64.

#define HH 512
#define WW 512

__device__ __forceinline__ float th(float x) {
    float y;
    asm("tanh.approx.f32 %0, %1;" : "=f"(y) : "f"(x));
    return y;
}

// tanh.approx.f16x2 on (a0, a1); accumulate w*tanh into f32 sums T[0], T[1]
__device__ __forceinline__ void acc2(float* T, float a0, float a1, float w = 1.0f) {
    __half2 h = __floats2half2_rn(a0, a1);
    unsigned uin, uout;
    uin = *reinterpret_cast<unsigned*>(&h);
    asm("tanh.approx.f16x2 %0, %1;" : "=r"(uout) : "r"(uin));
    __half2 t = *reinterpret_cast<__half2*>(&uout);
    float2 tf = __half22float2(t);
    T[0] = fmaf(w, tf.x, T[0]);
    T[1] = fmaf(w, tf.y, T[1]);
}

__device__ __forceinline__ float2 ldg2(const float* p) {
    return *reinterpret_cast<const float2*>(p);
}

__global__ void __launch_bounds__(256) edge_kernel(const float* __restrict__ in,
                                                   float* __restrict__ out) {
    int idx = blockIdx.x * blockDim.x + threadIdx.x;   // one thread = 2 pixels
    int x  = (idx & 255) << 1;         // even
    int y  = (idx >> 8) & (HH - 1);
    int bc = idx >> 17;                // b*3 + c
    int c  = bc - (bc / 3) * 3;
    int b  = bc / 3;

    float* o = out + (((b * 24 + c * 8) << 18) + (y << 9) + x);

    if (x < 2 || x >= WW - 2 || y < 2 || y >= HH - 2) {
        float2 z = make_float2(0.0f, 0.0f);
        #pragma unroll
        for (int k = 0; k < 8; k++) *reinterpret_cast<float2*>(o + (k << 18)) = z;
        return;
    }

    int cm = (c + 2) % 3;
    int cp = (c + 1) % 3;

    const float* p  = in + (bc << 18);
    const float* pa = in + ((b * 3 + cm) << 18);
    const float* pc = in + ((b * 3 + cp) << 18);

    int r   = (y << 9) + x;
    int rm1 = r - WW, rp1 = r + WW, rm2 = r - 2 * WW;

    const float S = 5.0f;

    // ---- loads (pre-scaled by 5) ----
    // own channel
    float2 Vm2 = ldg2(p + rm2);         Vm2.x *= S; Vm2.y *= S;
    float  um1L = S * __ldg(p + rm1 - 1);
    float2 Um1  = ldg2(p + rm1);        Um1.x *= S; Um1.y *= S;
    float  um1R = S * __ldg(p + rm1 + 2);
    float  u0L  = S * __ldg(p + r - 1);
    float2 U0   = ldg2(p + r);          U0.x  *= S; U0.y  *= S;
    float  u0R  = S * __ldg(p + r + 2);
    float  up1L = S * __ldg(p + rp1 - 1);
    float2 Up1  = ldg2(p + rp1);        Up1.x *= S; Up1.y *= S;
    float  up1R = S * __ldg(p + rp1 + 2);
    // channel cm
    float  aL  = S * __ldg(pa + r - 1);
    float2 A0  = ldg2(pa + r);          A0.x *= S; A0.y *= S;
    float  aR  = S * __ldg(pa + r + 2);
    float2 Am1 = ldg2(pa + rm1);        Am1.x *= S; Am1.y *= S;
    float  a2L = S * __ldg(pa + rm2 - 1);
    float2 A2  = ldg2(pa + rm2);        A2.x *= S; A2.y *= S;
    float  a2R = S * __ldg(pa + rm2 + 2);
    // channel cp
    float2 Cm1 = ldg2(pc + rm1);        Cm1.x *= S; Cm1.y *= S;
    float  c2L = S * __ldg(pc + rm2 - 1);
    float  c2C = S * __ldg(pc + rm2);
    float  c0L = S * __ldg(pc + r - 1);
    float  c0C = S * __ldg(pc + r);

    // ---- per-lane neighborhoods ----
    float v00[2]   = { U0.x,  U0.y  };
    float v0m1[2]  = { u0L,   U0.x  };
    float v0p1[2]  = { U0.y,  u0R   };
    float vm1m1[2] = { um1L,  Um1.x };
    float vm10[2]  = { Um1.x, Um1.y };
    float vm1p1[2] = { Um1.y, um1R  };
    float vp1m1[2] = { up1L,  Up1.x };
    float vp10[2]  = { Up1.x, Up1.y };
    float vp1p1[2] = { Up1.y, up1R  };
    float vm20[2]  = { Vm2.x, Vm2.y };
    float a00[2]   = { A0.x,  A0.y  };
    float a0m1[2]  = { aL,    A0.x  };
    float a0p1[2]  = { A0.y,  aR    };
    float am10[2]  = { Am1.x, Am1.y };
    float am2m1[2] = { a2L,   A2.x  };
    float am2p1[2] = { A2.y,  a2R   };
    float cm10[2]  = { Cm1.x, Cm1.y };
    float cm2m1[2] = { c2L,   c2C   };
    float c0m1[2]  = { c0L,   c0C   };

    // ---- diffs (scaled) ----
    float d10[2], dn10[2], d01[2], dn01[2], d11[2], dnn11[2], dn11[2], d1n1[2];
    float rd01a[2], rdn01a[2], rd10u[2], rdn10u[2], rd01u[2];
    float rdn11b[2], rd1n1b[2], rd11b[2], rd11c[2], rdn11c[2];
    #pragma unroll
    for (int i = 0; i < 2; i++) {
        d10[i]   = vm10[i]  - v00[i];
        dn10[i]  = vp10[i]  - v00[i];
        d01[i]   = v0m1[i]  - v00[i];
        dn01[i]  = v0p1[i]  - v00[i];
        d11[i]   = vm1m1[i] - v00[i];
        dnn11[i] = vp1p1[i] - v00[i];
        dn11[i]  = vp1m1[i] - v00[i];
        d1n1[i]  = vm1p1[i] - v00[i];
        rd01a[i]  = a0m1[i] - a00[i];      // rl(.,(1,0))
        rdn01a[i] = a0p1[i] - a00[i];
        rd10u[i]  = vm20[i]  - vm10[i];    // rl(.,(0,1))
        rdn10u[i] = v00[i]   - vm10[i];
        rd01u[i]  = vm1m1[i] - vm10[i];
        rdn11b[i] = a0m1[i]  - am10[i];    // rl(.,(1,1))
        rd1n1b[i] = am2p1[i] - am10[i];
        rd11b[i]  = am2m1[i] - am10[i];
        rd11c[i]  = cm2m1[i] - cm10[i];    // rl(.,(-1,1))
        rdn11c[i] = c0m1[i]  - cm10[i];
    }

    // ---- per-lane ad bases (f32 tanh) ----
    float ad10[2], thad10[2], ad01[2], ad11[2], adn11[2];
    #pragma unroll
    for (int i = 0; i < 2; i++) {
        float ad10r = fabsf(d10[i]);
        ad10[i]  = ad10r * fmaf(0.5f, th(ad10r), 0.5f);
        thad10[i] = th(ad10[i]);
        ad01[i]  = fabsf(d01[i]) * fmaf(0.5f, thad10[i], 0.5f);
        float ad11r = fabsf(d11[i]);
        ad11[i]  = ad11r * fmaf(0.5f, th(ad11r), 0.5f);
        adn11[i] = fabsf(dn11[i]);
    }

    // ---- e-sums: f16x2 tanh terms, f32 accumulation ----
    float T10[2] = {0.f, 0.f}, T01[2] = {0.f, 0.f}, T11[2] = {0.f, 0.f}, Tn11[2] = {0.f, 0.f};

    acc2(T10, ad10[0] - fabsf(d01[0]),   ad10[1] - fabsf(d01[1]));
    acc2(T10, ad10[0] - fabsf(dn01[0]),  ad10[1] - fabsf(dn01[1]));
    acc2(T10, ad10[0] - fabsf(dn10[0]),  ad10[1] - fabsf(dn10[1]));
    acc2(T10, ad10[0] - fabsf(rd01a[0]), ad10[1] - fabsf(rd01a[1]), 2.0f);
    acc2(T10, ad10[0] - fabsf(rdn01a[0]),ad10[1] - fabsf(rdn01a[1]));

    acc2(T01, ad01[0] - fabsf(d10[0]),   ad01[1] - fabsf(d10[1]));
    acc2(T01, ad01[0] - fabsf(dn10[0]),  ad01[1] - fabsf(dn10[1]));
    acc2(T01, ad01[0] - fabsf(dn01[0]),  ad01[1] - fabsf(dn01[1]));
    acc2(T01, ad01[0] - fabsf(rd10u[0]), ad01[1] - fabsf(rd10u[1]));
    acc2(T01, ad01[0] - fabsf(rdn10u[0]),ad01[1] - fabsf(rdn10u[1]));
    acc2(T01, ad01[0] - fabsf(rd01u[0]), ad01[1] - fabsf(rd01u[1]));

    acc2(T11, ad11[0] - fabsf(dn11[0]),  ad11[1] - fabsf(dn11[1]));
    acc2(T11, ad11[0] - fabsf(d1n1[0]),  ad11[1] - fabsf(d1n1[1]));
    acc2(T11, ad11[0] - fabsf(dnn11[0]), ad11[1] - fabsf(dnn11[1]));
    acc2(T11, ad11[0] - fabsf(rdn11b[0]),ad11[1] - fabsf(rdn11b[1]));
    acc2(T11, ad11[0] - fabsf(rd1n1b[0]),ad11[1] - fabsf(rd1n1b[1]));
    acc2(T11, ad11[0] - fabsf(rd11b[0]), ad11[1] - fabsf(rd11b[1]));

    acc2(Tn11, adn11[0] - fabsf(d11[0]),   adn11[1] - fabsf(d11[1]));
    acc2(Tn11, adn11[0] - fabsf(d1n1[0]),  adn11[1] - fabsf(d1n1[1]));
    acc2(Tn11, adn11[0] - fabsf(dnn11[0]), adn11[1] - fabsf(dnn11[1]));
    acc2(Tn11, adn11[0] - fabsf(rd11c[0]), adn11[1] - fabsf(rd11c[1]));
    acc2(Tn11, adn11[0] - fabsf(rdn11c[0]),adn11[1] - fabsf(rdn11c[1]), 2.0f);

    // ---- gates + outputs (f32) ----
    float2 O[8];
    #pragma unroll
    for (int i = 0; i < 2; i++) {
        float g10 = fmaf(0.5f, th(fmaf(2.5f, T10[i], -5.0f)), 0.5f);
        float s10 = fmaf(0.5f, th(d10[i]), 0.5f);
        float g01 = fmaf(0.5f, th(fmaf(2.5f, T01[i], -5.0f)), 0.5f);
        float s01 = fmaf(0.5f, th(d01[i]), 0.5f);
        float g11 = fmaf(0.5f, th(fmaf(2.5f, T11[i], -5.0f)), 0.5f);
        float s11 = fmaf(0.5f, th(d11[i]), 0.5f);
        float gn11 = fmaf(0.5f, th(fmaf(2.5f, Tn11[i], -5.0f)), 0.5f);
        float sn11 = fmaf(0.5f, th(dn11[i]), 0.5f);
        float e0 = g10 * s10;
        float e2 = g01 * s01;
        float e4 = g11 * s11;
        float e6 = gn11 * sn11;
        float* oi = i ? &O[0].y : &O[0].x;
        oi[0*2] = e0;        oi[1*2] = g10 - e0;
        oi[2*2] = e2;        oi[3*2] = e2;        // reference quirk: e01n == e01
        oi[4*2] = e4;        oi[5*2] = g11 - e4;
        oi[6*2] = e6;        oi[7*2] = gn11 - e6;
    }

    #pragma unroll
    for (int k = 0; k < 8; k++)
        *reinterpret_cast<float2*>(o + (k << 18)) = O[k];
}

extern "C" void kernel_launch(void* const* d_in, const int* in_sizes, int n_in,
                              void* d_out, int out_size) {
    const float* x = (const float*)d_in[0];
    float* out = (float*)d_out;
    int total_threads = 16 * 3 * HH * (WW / 2);
    edge_kernel<<<total_threads / 256, 256>>>(x, out);
}

// round 12
// speedup vs baseline: 1.0031x; 1.0028x over previous
#include <cuda_runtime.h>
#include <cuda_fp16.h>

// Edge_27547920236817: B=16, C=3, H=W=512 f32 in; out (B, C*8, H, W) f32.
// R7 (= R4 with compile fix): 2 x-adjacent pixels per thread; the 22 unique
// e-sum tanh terms computed as tanh.approx.f16x2 (args packed across the
// pixel pair), unpacked and summed in f32. Gates, sign sigmoids and
// ad-multiplier tanhs remain f32 MUFU.TANH.
// MUFU per pixel: 33 -> 22 (11 f16x2-halves + 11 f32).
// Memory instrs per pixel: 19 LDG + 8 STG -> 11 LDG + 4 STG.64.

#define HH 512
#define WW 512

__device__ __forceinline__ float th(float x) {
    float y;
    asm("tanh.approx.f32 %0, %1;" : "=f"(y) : "f"(x));
    return y;
}

// tanh.approx.f16x2 on (a0, a1); accumulate w*tanh into f32 sums T[0], T[1]
__device__ __forceinline__ void acc2(float* T, float a0, float a1, float w = 1.0f) {
    __half2 h = __floats2half2_rn(a0, a1);
    unsigned uin, uout;
    uin = *reinterpret_cast<unsigned*>(&h);
    asm("tanh.approx.f16x2 %0, %1;" : "=r"(uout) : "r"(uin));
    __half2 t = *reinterpret_cast<__half2*>(&uout);
    float2 tf = __half22float2(t);
    T[0] = fmaf(w, tf.x, T[0]);
    T[1] = fmaf(w, tf.y, T[1]);
}

__device__ __forceinline__ float2 ldg2(const float* p) {
    return *reinterpret_cast<const float2*>(p);
}

__global__ void __launch_bounds__(256) edge_kernel(const float* __restrict__ in,
                                                   float* __restrict__ out) {
    int idx = blockIdx.x * blockDim.x + threadIdx.x;   // one thread = 2 pixels
    int x  = (idx & 255) << 1;         // even
    int y  = (idx >> 8) & (HH - 1);
    int bc = idx >> 17;                // b*3 + c
    int c  = bc - (bc / 3) * 3;
    int b  = bc / 3;

    float* o = out + (((b * 24 + c * 8) << 18) + (y << 9) + x);

    if (x < 2 || x >= WW - 2 || y < 2 || y >= HH - 2) {
        float2 z = make_float2(0.0f, 0.0f);
        #pragma unroll
        for (int k = 0; k < 8; k++) *reinterpret_cast<float2*>(o + (k << 18)) = z;
        return;
    }

    int cm = (c + 2) % 3;
    int cp = (c + 1) % 3;

    const float* p  = in + (bc << 18);
    const float* pa = in + ((b * 3 + cm) << 18);
    const float* pc = in + ((b * 3 + cp) << 18);

    int r   = (y << 9) + x;
    int rm1 = r - WW, rp1 = r + WW, rm2 = r - 2 * WW;

    const float S = 5.0f;

    // ---- loads (pre-scaled by 5) ----
    // own channel
    float2 Vm2 = ldg2(p + rm2);         Vm2.x *= S; Vm2.y *= S;
    float  um1L = S * __ldg(p + rm1 - 1);
    float2 Um1  = ldg2(p + rm1);        Um1.x *= S; Um1.y *= S;
    float  um1R = S * __ldg(p + rm1 + 2);
    float  u0L  = S * __ldg(p + r - 1);
    float2 U0   = ldg2(p + r);          U0.x  *= S; U0.y  *= S;
    float  u0R  = S * __ldg(p + r + 2);
    float  up1L = S * __ldg(p + rp1 - 1);
    float2 Up1  = ldg2(p + rp1);        Up1.x *= S; Up1.y *= S;
    float  up1R = S * __ldg(p + rp1 + 2);
    // channel cm
    float  aL  = S * __ldg(pa + r - 1);
    float2 A0  = ldg2(pa + r);          A0.x *= S; A0.y *= S;
    float  aR  = S * __ldg(pa + r + 2);
    float2 Am1 = ldg2(pa + rm1);        Am1.x *= S; Am1.y *= S;
    float  a2L = S * __ldg(pa + rm2 - 1);
    float2 A2  = ldg2(pa + rm2);        A2.x *= S; A2.y *= S;
    float  a2R = S * __ldg(pa + rm2 + 2);
    // channel cp
    float2 Cm1 = ldg2(pc + rm1);        Cm1.x *= S; Cm1.y *= S;
    float  c2L = S * __ldg(pc + rm2 - 1);
    float  c2C = S * __ldg(pc + rm2);
    float  c0L = S * __ldg(pc + r - 1);
    float  c0C = S * __ldg(pc + r);

    // ---- per-lane neighborhoods ----
    float v00[2]   = { U0.x,  U0.y  };
    float v0m1[2]  = { u0L,   U0.x  };
    float v0p1[2]  = { U0.y,  u0R   };
    float vm1m1[2] = { um1L,  Um1.x };
    float vm10[2]  = { Um1.x, Um1.y };
    float vm1p1[2] = { Um1.y, um1R  };
    float vp1m1[2] = { up1L,  Up1.x };
    float vp10[2]  = { Up1.x, Up1.y };
    float vp1p1[2] = { Up1.y, up1R  };
    float vm20[2]  = { Vm2.x, Vm2.y };
    float a00[2]   = { A0.x,  A0.y  };
    float a0m1[2]  = { aL,    A0.x  };
    float a0p1[2]  = { A0.y,  aR    };
    float am10[2]  = { Am1.x, Am1.y };
    float am2m1[2] = { a2L,   A2.x  };
    float am2p1[2] = { A2.y,  a2R   };
    float cm10[2]  = { Cm1.x, Cm1.y };
    float cm2m1[2] = { c2L,   c2C   };
    float c0m1[2]  = { c0L,   c0C   };

    // ---- diffs (scaled) ----
    float d10[2], dn10[2], d01[2], dn01[2], d11[2], dnn11[2], dn11[2], d1n1[2];
    float rd01a[2], rdn01a[2], rd10u[2], rdn10u[2], rd01u[2];
    float rdn11b[2], rd1n1b[2], rd11b[2], rd11c[2], rdn11c[2];
    #pragma unroll
    for (int i = 0; i < 2; i++) {
        d10[i]   = vm10[i]  - v00[i];
        dn10[i]  = vp10[i]  - v00[i];
        d01[i]   = v0m1[i]  - v00[i];
        dn01[i]  = v0p1[i]  - v00[i];
        d11[i]   = vm1m1[i] - v00[i];
        dnn11[i] = vp1p1[i] - v00[i];
        dn11[i]  = vp1m1[i] - v00[i];
        d1n1[i]  = vm1p1[i] - v00[i];
        rd01a[i]  = a0m1[i] - a00[i];      // rl(.,(1,0))
        rdn01a[i] = a0p1[i] - a00[i];
        rd10u[i]  = vm20[i]  - vm10[i];    // rl(.,(0,1))
        rdn10u[i] = v00[i]   - vm10[i];
        rd01u[i]  = vm1m1[i] - vm10[i];
        rdn11b[i] = a0m1[i]  - am10[i];    // rl(.,(1,1))
        rd1n1b[i] = am2p1[i] - am10[i];
        rd11b[i]  = am2m1[i] - am10[i];
        rd11c[i]  = cm2m1[i] - cm10[i];    // rl(.,(-1,1))
        rdn11c[i] = c0m1[i]  - cm10[i];
    }

    // ---- per-lane ad bases (f32 tanh) ----
    float ad10[2], thad10[2], ad01[2], ad11[2], adn11[2];
    #pragma unroll
    for (int i = 0; i < 2; i++) {
        float ad10r = fabsf(d10[i]);
        ad10[i]  = ad10r * fmaf(0.5f, th(ad10r), 0.5f);
        thad10[i] = th(ad10[i]);
        ad01[i]  = fabsf(d01[i]) * fmaf(0.5f, thad10[i], 0.5f);
        float ad11r = fabsf(d11[i]);
        ad11[i]  = ad11r * fmaf(0.5f, th(ad11r), 0.5f);
        adn11[i] = fabsf(dn11[i]);
    }

    // ---- e-sums: f16x2 tanh terms, f32 accumulation ----
    float T10[2] = {0.f, 0.f}, T01[2] = {0.f, 0.f}, T11[2] = {0.f, 0.f}, Tn11[2] = {0.f, 0.f};

    acc2(T10, ad10[0] - fabsf(d01[0]),   ad10[1] - fabsf(d01[1]));
    acc2(T10, ad10[0] - fabsf(dn01[0]),  ad10[1] - fabsf(dn01[1]));
    acc2(T10, ad10[0] - fabsf(dn10[0]),  ad10[1] - fabsf(dn10[1]));
    acc2(T10, ad10[0] - fabsf(rd01a[0]), ad10[1] - fabsf(rd01a[1]), 2.0f);
    acc2(T10, ad10[0] - fabsf(rdn01a[0]),ad10[1] - fabsf(rdn01a[1]));

    acc2(T01, ad01[0] - fabsf(d10[0]),   ad01[1] - fabsf(d10[1]));
    acc2(T01, ad01[0] - fabsf(dn10[0]),  ad01[1] - fabsf(dn10[1]));
    acc2(T01, ad01[0] - fabsf(dn01[0]),  ad01[1] - fabsf(dn01[1]));
    acc2(T01, ad01[0] - fabsf(rd10u[0]), ad01[1] - fabsf(rd10u[1]));
    acc2(T01, ad01[0] - fabsf(rdn10u[0]),ad01[1] - fabsf(rdn10u[1]));
    acc2(T01, ad01[0] - fabsf(rd01u[0]), ad01[1] - fabsf(rd01u[1]));

    acc2(T11, ad11[0] - fabsf(dn11[0]),  ad11[1] - fabsf(dn11[1]));
    acc2(T11, ad11[0] - fabsf(d1n1[0]),  ad11[1] - fabsf(d1n1[1]));
    acc2(T11, ad11[0] - fabsf(dnn11[0]), ad11[1] - fabsf(dnn11[1]));
    acc2(T11, ad11[0] - fabsf(rdn11b[0]),ad11[1] - fabsf(rdn11b[1]));
    acc2(T11, ad11[0] - fabsf(rd1n1b[0]),ad11[1] - fabsf(rd1n1b[1]));
    acc2(T11, ad11[0] - fabsf(rd11b[0]), ad11[1] - fabsf(rd11b[1]));

    acc2(Tn11, adn11[0] - fabsf(d11[0]),   adn11[1] - fabsf(d11[1]));
    acc2(Tn11, adn11[0] - fabsf(d1n1[0]),  adn11[1] - fabsf(d1n1[1]));
    acc2(Tn11, adn11[0] - fabsf(dnn11[0]), adn11[1] - fabsf(dnn11[1]));
    acc2(Tn11, adn11[0] - fabsf(rd11c[0]), adn11[1] - fabsf(rd11c[1]));
    acc2(Tn11, adn11[0] - fabsf(rdn11c[0]),adn11[1] - fabsf(rdn11c[1]), 2.0f);

    // ---- gates + outputs (f32) ----
    float2 O[8];
    #pragma unroll
    for (int i = 0; i < 2; i++) {
        float g10 = fmaf(0.5f, th(fmaf(2.5f, T10[i], -5.0f)), 0.5f);
        float s10 = fmaf(0.5f, th(d10[i]), 0.5f);
        float g01 = fmaf(0.5f, th(fmaf(2.5f, T01[i], -5.0f)), 0.5f);
        float s01 = fmaf(0.5f, th(d01[i]), 0.5f);
        float g11 = fmaf(0.5f, th(fmaf(2.5f, T11[i], -5.0f)), 0.5f);
        float s11 = fmaf(0.5f, th(d11[i]), 0.5f);
        float gn11 = fmaf(0.5f, th(fmaf(2.5f, Tn11[i], -5.0f)), 0.5f);
        float sn11 = fmaf(0.5f, th(dn11[i]), 0.5f);
        float e0 = g10 * s10;
        float e2 = g01 * s01;
        float e4 = g11 * s11;
        float e6 = gn11 * sn11;
        float* oi = i ? &O[0].y : &O[0].x;
        oi[0*2] = e0;        oi[1*2] = g10 - e0;
        oi[2*2] = e2;        oi[3*2] = e2;        // reference quirk: e01n == e01
        oi[4*2] = e4;        oi[5*2] = g11 - e4;
        oi[6*2] = e6;        oi[7*2] = gn11 - e6;
    }

    #pragma unroll
    for (int k = 0; k < 8; k++)
        *reinterpret_cast<float2*>(o + (k << 18)) = O[k];
}

extern "C" void kernel_launch(void* const* d_in, const int* in_sizes, int n_in,
                              void* d_out, int out_size) {
    const float* x = (const float*)d_in[0];
    float* out = (float*)d_out;
    int total_threads = 16 * 3 * HH * (WW / 2);
    edge_kernel<<<total_threads / 256, 256>>>(x, out);
}